// round 8
// baseline (speedup 1.0000x reference)
#include <cuda_runtime.h>
#include <math.h>
#include <float.h>

// Problem constants
#define NN   1024
#define FF   64
#define DD   64
#define TK   20
#define BB   64
#define EPSBN 1e-5f
#define NEG  0.2f

// Scratch (device globals: allocation-free)
__device__ float d_xl[BB*NN*DD];     // 16 MB
__device__ float d_gnn[BB*NN*DD];    // 16 MB
__device__ float d_S[NN*NN];         // 4 MB  cosine-equivalent scores
__device__ float d_u[NN*DD];         // normalized embedding rows
__device__ float d_ai[BB*NN];
__device__ float d_aj[BB*NN];
__device__ float d_aemi[NN];
__device__ float d_aemj[NN];
__device__ int   d_topi[NN*TK];
__device__ float d_stats[5*DD];      // Sg, Sgg, Sge, Sge2, Sgge2
__device__ float d_params[4*DD];     // A1, C1, A2, C2

// ---------------------------------------------------------------------------
// k_prep: per-node norm, u = w/||w||, aem_i = w.att_em_i, aem_j = w.att_em_j.
// Block 0 also zeroes the stats accumulator (replay-safe: runs every launch).
// ---------------------------------------------------------------------------
__global__ void k_prep(const float* __restrict__ emb,
                       const float* __restrict__ att_em_i,
                       const float* __restrict__ att_em_j) {
    int j = blockIdx.x, d = threadIdx.x;
    if (blockIdx.x == 0) {
        for (int i = threadIdx.x; i < 5*DD; i += 64) d_stats[i] = 0.f;
    }
    float v  = emb[j*DD + d];
    float p0 = v*v;
    float p1 = v*att_em_i[d];
    float p2 = v*att_em_j[d];
    #pragma unroll
    for (int off = 16; off; off >>= 1) {
        p0 += __shfl_down_sync(0xffffffffu, p0, off);
        p1 += __shfl_down_sync(0xffffffffu, p1, off);
        p2 += __shfl_down_sync(0xffffffffu, p2, off);
    }
    __shared__ float w0[2], w1[2], w2[2];
    int lane = d & 31, wrp = d >> 5;
    if (lane == 0) { w0[wrp] = p0; w1[wrp] = p1; w2[wrp] = p2; }
    __syncthreads();
    float nrm2 = w0[0] + w0[1];
    float inv  = rsqrtf(nrm2);
    d_u[j*DD + d] = v * inv;
    if (d == 0) {
        d_aemi[j] = w1[0] + w1[1];
        d_aemj[j] = w2[0] + w2[1];
    }
}

// ---------------------------------------------------------------------------
// k_scores: S = emb @ u^T  (1024x1024x64). 64x64 output tile per block.
// ---------------------------------------------------------------------------
__global__ void k_scores(const float* __restrict__ emb) {
    __shared__ __align__(16) float As[64][68];   // As[d][row]
    __shared__ __align__(16) float Bs[64][68];   // Bs[d][col]
    int i0 = blockIdx.y * 64, j0 = blockIdx.x * 64;
    int tid = threadIdx.x;
    for (int idx = tid; idx < 4096; idx += 256) {
        int r = idx >> 6, dd = idx & 63;
        As[dd][r] = emb[(i0 + r)*DD + dd];
        Bs[dd][r] = d_u[(j0 + r)*DD + dd];
    }
    __syncthreads();
    int tx = tid & 15, ty = tid >> 4;
    float acc[4][4] = {};
    #pragma unroll
    for (int dd = 0; dd < 64; dd++) {
        float4 a = *(const float4*)&As[dd][ty*4];
        float4 b = *(const float4*)&Bs[dd][tx*4];
        acc[0][0] += a.x*b.x; acc[0][1] += a.x*b.y; acc[0][2] += a.x*b.z; acc[0][3] += a.x*b.w;
        acc[1][0] += a.y*b.x; acc[1][1] += a.y*b.y; acc[1][2] += a.y*b.z; acc[1][3] += a.y*b.w;
        acc[2][0] += a.z*b.x; acc[2][1] += a.z*b.y; acc[2][2] += a.z*b.z; acc[2][3] += a.z*b.w;
        acc[3][0] += a.w*b.x; acc[3][1] += a.w*b.y; acc[3][2] += a.w*b.z; acc[3][3] += a.w*b.w;
    }
    #pragma unroll
    for (int i = 0; i < 4; i++) {
        float4 v = make_float4(acc[i][0], acc[i][1], acc[i][2], acc[i][3]);
        *(float4*)&d_S[(i0 + ty*4 + i)*NN + j0 + tx*4] = v;
    }
}

// ---------------------------------------------------------------------------
// k_topk: per-row top-20 by iterative argmax (tie -> lowest index, jax-compat).
// ---------------------------------------------------------------------------
__global__ void k_topk() {
    __shared__ float s[NN];
    __shared__ float bv[256];
    __shared__ int   bi[256];
    int row = blockIdx.x, tid = threadIdx.x;
    for (int j = tid; j < NN; j += 256) s[j] = d_S[row*NN + j];
    __syncthreads();
    for (int t = 0; t < TK; t++) {
        float best = -FLT_MAX; int bidx = NN;
        for (int j = tid; j < NN; j += 256) {
            float v = s[j];
            if (v > best) { best = v; bidx = j; }   // strict > keeps smallest j on ties
        }
        bv[tid] = best; bi[tid] = bidx;
        __syncthreads();
        #pragma unroll
        for (int off = 128; off; off >>= 1) {
            if (tid < off) {
                float v = bv[tid + off]; int i2 = bi[tid + off];
                if (v > bv[tid] || (v == bv[tid] && i2 < bi[tid])) { bv[tid] = v; bi[tid] = i2; }
            }
            __syncthreads();
        }
        if (tid == 0) { d_topi[row*TK + t] = bi[0]; s[bi[0]] = -FLT_MAX; }
        __syncthreads();
    }
}

// ---------------------------------------------------------------------------
// k_xl: xl = data @ lin_w (65536x64 @ 64x64), fused per-row dots with
// att_i / att_j. 64 rows per block, 4x4 register tile per thread.
// ---------------------------------------------------------------------------
__global__ void k_xl(const float* __restrict__ data, const float* __restrict__ lw,
                     const float* __restrict__ att_i, const float* __restrict__ att_j) {
    __shared__ __align__(16) float Ws[64][64];   // Ws[f][c]
    __shared__ __align__(16) float Dt[64][68];   // Dt[f][r]
    __shared__ float atti[64], attj[64], redI[64], redJ[64];
    int tid = threadIdx.x;
    int row0 = blockIdx.x * 64;
    for (int idx = tid; idx < 4096; idx += 256) {
        ((float*)Ws)[idx] = lw[idx];
        int r = idx >> 6, f = idx & 63;
        Dt[f][r] = data[(row0 + r)*FF + f];
    }
    if (tid < 64) { atti[tid] = att_i[tid]; attj[tid] = att_j[tid]; redI[tid] = 0.f; redJ[tid] = 0.f; }
    __syncthreads();
    int tx = tid & 15, ty = tid >> 4;
    float acc[4][4] = {};
    #pragma unroll
    for (int f = 0; f < 64; f++) {
        float4 a = *(const float4*)&Dt[f][ty*4];
        float4 b = *(const float4*)&Ws[f][tx*4];
        acc[0][0] += a.x*b.x; acc[0][1] += a.x*b.y; acc[0][2] += a.x*b.z; acc[0][3] += a.x*b.w;
        acc[1][0] += a.y*b.x; acc[1][1] += a.y*b.y; acc[1][2] += a.y*b.z; acc[1][3] += a.y*b.w;
        acc[2][0] += a.z*b.x; acc[2][1] += a.z*b.y; acc[2][2] += a.z*b.z; acc[2][3] += a.z*b.w;
        acc[3][0] += a.w*b.x; acc[3][1] += a.w*b.y; acc[3][2] += a.w*b.z; acc[3][3] += a.w*b.w;
    }
    #pragma unroll
    for (int i = 0; i < 4; i++) {
        int gr = row0 + ty*4 + i;
        float4 v = make_float4(acc[i][0], acc[i][1], acc[i][2], acc[i][3]);
        *(float4*)&d_xl[gr*DD + tx*4] = v;
        int c0 = tx*4;
        float pai = acc[i][0]*atti[c0] + acc[i][1]*atti[c0+1] + acc[i][2]*atti[c0+2] + acc[i][3]*atti[c0+3];
        float paj = acc[i][0]*attj[c0] + acc[i][1]*attj[c0+1] + acc[i][2]*attj[c0+2] + acc[i][3]*attj[c0+3];
        atomicAdd(&redI[ty*4 + i], pai);
        atomicAdd(&redJ[ty*4 + i], paj);
    }
    __syncthreads();
    if (tid < 64) { d_ai[row0 + tid] = redI[tid]; d_aj[row0 + tid] = redJ[tid]; }
}

// ---------------------------------------------------------------------------
// k_gnn: scores -> leaky_relu -> softmax(20) -> weighted neighbor sum + bias.
// Fused accumulation of the 5 per-d moments needed for bn1 AND bn2 (analytic).
// Block = 256 threads, 64 (b,n) rows per block (4 concurrent x 16 iters).
// ---------------------------------------------------------------------------
__global__ void k_gnn(const float* __restrict__ emb, const float* __restrict__ gnn_bias) {
    __shared__ float scs[4][TK];
    __shared__ float es [4][TK];
    __shared__ int   idxs[4][TK];
    __shared__ float gb[64];
    __shared__ float sred[5*64];
    int tid = threadIdx.x;
    if (tid < 64) gb[tid] = gnn_bias[tid];
    for (int i = tid; i < 5*64; i += 256) sred[i] = 0.f;
    int r4 = tid >> 6, d = tid & 63;
    float sg = 0.f, sgg = 0.f, sge = 0.f, sge2 = 0.f, sgge2 = 0.f;
    __syncthreads();
    for (int it = 0; it < 16; it++) {
        int m = blockIdx.x*64 + it*4 + r4;
        int b = m >> 10, n = m & 1023;
        if (d < TK) {
            int idx = d_topi[n*TK + d];
            float sc = d_ai[m] + d_aemi[n] + d_aj[(b << 10) + idx] + d_aemj[idx];
            sc = sc > 0.f ? sc : NEG*sc;
            scs[r4][d] = sc; idxs[r4][d] = idx;
        }
        __syncthreads();
        if (d < TK) {
            float mx = -FLT_MAX;
            #pragma unroll
            for (int k = 0; k < TK; k++) mx = fmaxf(mx, scs[r4][k]);
            es[r4][d] = __expf(scs[r4][d] - mx);
        }
        __syncthreads();
        float ssum = 0.f;
        #pragma unroll
        for (int k = 0; k < TK; k++) ssum += es[r4][k];
        float inv = 1.f / ssum;
        float acc = 0.f;
        #pragma unroll
        for (int k = 0; k < TK; k++) {
            int idx = idxs[r4][k];
            acc += es[r4][k] * d_xl[((b << 10) + idx)*DD + d];
        }
        float g = acc*inv + gb[d];
        d_gnn[m*DD + d] = g;
        float e  = emb[(n << 6) + d];
        float ge = g*e;
        sg += g; sgg += g*g; sge += ge; sge2 += ge*e; sgge2 += ge*ge;
        __syncthreads();
    }
    atomicAdd(&sred[0*64 + d], sg);
    atomicAdd(&sred[1*64 + d], sgg);
    atomicAdd(&sred[2*64 + d], sge);
    atomicAdd(&sred[3*64 + d], sge2);
    atomicAdd(&sred[4*64 + d], sgge2);
    __syncthreads();
    for (int i = tid; i < 5*64; i += 256) atomicAdd(&d_stats[i], sred[i]);
}

// ---------------------------------------------------------------------------
// k_params: finalize bn1 affine (A1,C1) and bn2 affine (A2,C2) analytically.
//   t = (A1*g + C1) * e ;  E[t], E[t^2] from the 5 g-moments + emb moments.
// ---------------------------------------------------------------------------
__global__ void k_params(const float* __restrict__ emb,
                         const float* __restrict__ g1, const float* __restrict__ b1,
                         const float* __restrict__ g2, const float* __restrict__ b2) {
    __shared__ float sE[4][64], sE2[4][64];
    int tid = threadIdx.x, d = tid & 63, grp = tid >> 6;
    float se = 0.f, see = 0.f;
    for (int n = grp; n < NN; n += 4) {
        float e = emb[n*DD + d];
        se += e; see += e*e;
    }
    sE[grp][d] = se; sE2[grp][d] = see;
    __syncthreads();
    if (tid < 64) {
        float Se  = (sE[0][d] + sE[1][d] + sE[2][d] + sE[3][d]) * (float)BB;
        float See = (sE2[0][d] + sE2[1][d] + sE2[2][d] + sE2[3][d]) * (float)BB;
        const float Minv = 1.f / (float)(BB*NN);
        float Sg    = d_stats[0*64 + d];
        float Sgg   = d_stats[1*64 + d];
        float Sge   = d_stats[2*64 + d];
        float Sge2  = d_stats[3*64 + d];
        float Sgge2 = d_stats[4*64 + d];
        float mu1 = Sg * Minv;
        float var1 = Sgg * Minv - mu1*mu1;
        float A1 = g1[d] * rsqrtf(var1 + EPSBN);
        float C1 = b1[d] - A1*mu1;
        float mu2 = (A1*Sge + C1*Se) * Minv;
        float Et2 = (A1*A1*Sgge2 + 2.f*A1*C1*Sge2 + C1*C1*See) * Minv;
        float var2 = Et2 - mu2*mu2;
        float A2 = g2[d] * rsqrtf(var2 + EPSBN);
        float C2 = b2[d] - A2*mu2;
        d_params[0*64 + d] = A1; d_params[1*64 + d] = C1;
        d_params[2*64 + d] = A2; d_params[3*64 + d] = C2;
    }
}

// ---------------------------------------------------------------------------
// k_out: out = relu(A2*((A1*g+C1)*e)+C2), pred = out . out_w + out_b.
// ---------------------------------------------------------------------------
__global__ void k_out(const float* __restrict__ emb, const float* __restrict__ out_w,
                      const float* __restrict__ out_b,
                      float* __restrict__ pred, float* __restrict__ outbuf) {
    __shared__ float A1[64], C1[64], A2[64], C2[64], ow[64];
    __shared__ float wp[8];
    int tid = threadIdx.x;
    if (tid < 64) {
        A1[tid] = d_params[0*64 + tid]; C1[tid] = d_params[1*64 + tid];
        A2[tid] = d_params[2*64 + tid]; C2[tid] = d_params[3*64 + tid];
        ow[tid] = out_w[tid];
    }
    __syncthreads();
    int r4 = tid >> 6, d = tid & 63, lane = tid & 31, w = tid >> 5;
    float ob = out_b[0];
    for (int it = 0; it < 16; it++) {
        int m = blockIdx.x*64 + it*4 + r4;
        int n = m & 1023;
        float g = d_gnn[m*DD + d];
        float e = emb[(n << 6) + d];
        float t = (A1[d]*g + C1[d]) * e;
        float o = fmaxf(fmaf(A2[d], t, C2[d]), 0.f);
        outbuf[m*DD + d] = o;
        float pr = o * ow[d];
        #pragma unroll
        for (int off = 16; off; off >>= 1) pr += __shfl_down_sync(0xffffffffu, pr, off);
        if (lane == 0) wp[w] = pr;
        __syncthreads();
        if (tid < 4) pred[blockIdx.x*64 + it*4 + tid] = wp[2*tid] + wp[2*tid + 1] + ob;
        __syncthreads();
    }
}

// ---------------------------------------------------------------------------
extern "C" void kernel_launch(void* const* d_in, const int* in_sizes, int n_in,
                              void* d_out, int out_size) {
    const float* data     = (const float*)d_in[0];
    // d_in[1] = org_edge_index (unused by the reference)
    const float* emb      = (const float*)d_in[2];
    const float* lin_w    = (const float*)d_in[3];
    const float* att_i    = (const float*)d_in[4];
    const float* att_j    = (const float*)d_in[5];
    const float* att_em_i = (const float*)d_in[6];
    const float* att_em_j = (const float*)d_in[7];
    const float* gnn_bias = (const float*)d_in[8];
    const float* bn1g     = (const float*)d_in[9];
    const float* bn1b     = (const float*)d_in[10];
    const float* bn2g     = (const float*)d_in[11];
    const float* bn2b     = (const float*)d_in[12];
    const float* out_w    = (const float*)d_in[13];
    const float* out_b    = (const float*)d_in[14];

    float* pred = (float*)d_out;              // (B,N)   = 65536 floats
    float* outb = (float*)d_out + BB*NN;      // (B,N,D) = 4194304 floats

    k_prep  <<<NN, 64>>>(emb, att_em_i, att_em_j);
    k_scores<<<dim3(16,16), 256>>>(emb);
    k_topk  <<<NN, 256>>>();
    k_xl    <<<1024, 256>>>(data, lin_w, att_i, att_j);
    k_gnn   <<<1024, 256>>>(emb, gnn_bias);
    k_params<<<1, 256>>>(emb, bn1g, bn1b, bn2g, bn2b);
    k_out   <<<1024, 256>>>(emb, out_w, out_b, pred, outb);
}

// round 9
// speedup vs baseline: 1.0508x; 1.0508x over previous
#include <cuda_runtime.h>
#include <math.h>
#include <float.h>

// Problem constants
#define NN   1024
#define FF   64
#define DD   64
#define TK   20
#define BB   64
#define EPSBN 1e-5f
#define NEG  0.2f

// Scratch (device globals: allocation-free)
__device__ float d_xl[BB*NN*DD];     // 16 MB
__device__ float d_gnn[BB*NN*DD];    // 16 MB
__device__ float d_S[NN*NN];         // 4 MB  cosine-equivalent scores
__device__ float d_u[NN*DD];         // normalized embedding rows
__device__ float d_ai[BB*NN];
__device__ float d_aj[BB*NN];
__device__ float d_aemi[NN];
__device__ float d_aemj[NN];
__device__ int   d_topi[NN*TK];
__device__ float d_stats[5*DD];      // Sg, Sgg, Sge, Sge2, Sgge2
__device__ float d_params[4*DD];     // A1, C1, A2, C2

// ---------------------------------------------------------------------------
// k_prep: per-node norm, u = w/||w||, aem_i = w.att_em_i, aem_j = w.att_em_j.
// Block 0 also zeroes the stats accumulator (replay-safe: runs every launch).
// ---------------------------------------------------------------------------
__global__ void k_prep(const float* __restrict__ emb,
                       const float* __restrict__ att_em_i,
                       const float* __restrict__ att_em_j) {
    int j = blockIdx.x, d = threadIdx.x;
    if (blockIdx.x == 0) {
        for (int i = threadIdx.x; i < 5*DD; i += 64) d_stats[i] = 0.f;
    }
    float v  = emb[j*DD + d];
    float p0 = v*v;
    float p1 = v*att_em_i[d];
    float p2 = v*att_em_j[d];
    #pragma unroll
    for (int off = 16; off; off >>= 1) {
        p0 += __shfl_down_sync(0xffffffffu, p0, off);
        p1 += __shfl_down_sync(0xffffffffu, p1, off);
        p2 += __shfl_down_sync(0xffffffffu, p2, off);
    }
    __shared__ float w0[2], w1[2], w2[2];
    int lane = d & 31, wrp = d >> 5;
    if (lane == 0) { w0[wrp] = p0; w1[wrp] = p1; w2[wrp] = p2; }
    __syncthreads();
    float nrm2 = w0[0] + w0[1];
    float inv  = rsqrtf(nrm2);
    d_u[j*DD + d] = v * inv;
    if (d == 0) {
        d_aemi[j] = w1[0] + w1[1];
        d_aemj[j] = w2[0] + w2[1];
    }
}

// ---------------------------------------------------------------------------
// k_scores: S = emb @ u^T  (1024x1024x64). 64x64 output tile per block.
// ---------------------------------------------------------------------------
__global__ void k_scores(const float* __restrict__ emb) {
    __shared__ __align__(16) float As[64][68];   // As[d][row]
    __shared__ __align__(16) float Bs[64][68];   // Bs[d][col]
    int i0 = blockIdx.y * 64, j0 = blockIdx.x * 64;
    int tid = threadIdx.x;
    for (int idx = tid; idx < 4096; idx += 256) {
        int r = idx >> 6, dd = idx & 63;
        As[dd][r] = emb[(i0 + r)*DD + dd];
        Bs[dd][r] = d_u[(j0 + r)*DD + dd];
    }
    __syncthreads();
    int tx = tid & 15, ty = tid >> 4;
    float acc[4][4] = {};
    #pragma unroll
    for (int dd = 0; dd < 64; dd++) {
        float4 a = *(const float4*)&As[dd][ty*4];
        float4 b = *(const float4*)&Bs[dd][tx*4];
        acc[0][0] += a.x*b.x; acc[0][1] += a.x*b.y; acc[0][2] += a.x*b.z; acc[0][3] += a.x*b.w;
        acc[1][0] += a.y*b.x; acc[1][1] += a.y*b.y; acc[1][2] += a.y*b.z; acc[1][3] += a.y*b.w;
        acc[2][0] += a.z*b.x; acc[2][1] += a.z*b.y; acc[2][2] += a.z*b.z; acc[2][3] += a.z*b.w;
        acc[3][0] += a.w*b.x; acc[3][1] += a.w*b.y; acc[3][2] += a.w*b.z; acc[3][3] += a.w*b.w;
    }
    #pragma unroll
    for (int i = 0; i < 4; i++) {
        float4 v = make_float4(acc[i][0], acc[i][1], acc[i][2], acc[i][3]);
        *(float4*)&d_S[(i0 + ty*4 + i)*NN + j0 + tx*4] = v;
    }
}

// ---------------------------------------------------------------------------
// k_topk: per-row top-20 by iterative argmax (tie -> lowest index, jax-compat).
// ---------------------------------------------------------------------------
__global__ void k_topk() {
    __shared__ float s[NN];
    __shared__ float bv[256];
    __shared__ int   bi[256];
    int row = blockIdx.x, tid = threadIdx.x;
    for (int j = tid; j < NN; j += 256) s[j] = d_S[row*NN + j];
    __syncthreads();
    for (int t = 0; t < TK; t++) {
        float best = -FLT_MAX; int bidx = NN;
        for (int j = tid; j < NN; j += 256) {
            float v = s[j];
            if (v > best) { best = v; bidx = j; }   // strict > keeps smallest j on ties
        }
        bv[tid] = best; bi[tid] = bidx;
        __syncthreads();
        #pragma unroll
        for (int off = 128; off; off >>= 1) {
            if (tid < off) {
                float v = bv[tid + off]; int i2 = bi[tid + off];
                if (v > bv[tid] || (v == bv[tid] && i2 < bi[tid])) { bv[tid] = v; bi[tid] = i2; }
            }
            __syncthreads();
        }
        if (tid == 0) { d_topi[row*TK + t] = bi[0]; s[bi[0]] = -FLT_MAX; }
        __syncthreads();
    }
}

// ---------------------------------------------------------------------------
// k_xl: xl = data @ lin_w (65536x64 @ 64x64), fused per-row dots with
// att_i / att_j. 64 rows per block, 4x4 register tile per thread.
// ---------------------------------------------------------------------------
__global__ void k_xl(const float* __restrict__ data, const float* __restrict__ lw,
                     const float* __restrict__ att_i, const float* __restrict__ att_j) {
    __shared__ __align__(16) float Ws[64][64];   // Ws[f][c]
    __shared__ __align__(16) float Dt[64][68];   // Dt[f][r]
    __shared__ float atti[64], attj[64], redI[64], redJ[64];
    int tid = threadIdx.x;
    int row0 = blockIdx.x * 64;
    for (int idx = tid; idx < 4096; idx += 256) {
        ((float*)Ws)[idx] = lw[idx];
        int r = idx >> 6, f = idx & 63;
        Dt[f][r] = data[(row0 + r)*FF + f];
    }
    if (tid < 64) { atti[tid] = att_i[tid]; attj[tid] = att_j[tid]; redI[tid] = 0.f; redJ[tid] = 0.f; }
    __syncthreads();
    int tx = tid & 15, ty = tid >> 4;
    float acc[4][4] = {};
    #pragma unroll
    for (int f = 0; f < 64; f++) {
        float4 a = *(const float4*)&Dt[f][ty*4];
        float4 b = *(const float4*)&Ws[f][tx*4];
        acc[0][0] += a.x*b.x; acc[0][1] += a.x*b.y; acc[0][2] += a.x*b.z; acc[0][3] += a.x*b.w;
        acc[1][0] += a.y*b.x; acc[1][1] += a.y*b.y; acc[1][2] += a.y*b.z; acc[1][3] += a.y*b.w;
        acc[2][0] += a.z*b.x; acc[2][1] += a.z*b.y; acc[2][2] += a.z*b.z; acc[2][3] += a.z*b.w;
        acc[3][0] += a.w*b.x; acc[3][1] += a.w*b.y; acc[3][2] += a.w*b.z; acc[3][3] += a.w*b.w;
    }
    #pragma unroll
    for (int i = 0; i < 4; i++) {
        int gr = row0 + ty*4 + i;
        float4 v = make_float4(acc[i][0], acc[i][1], acc[i][2], acc[i][3]);
        *(float4*)&d_xl[gr*DD + tx*4] = v;
        int c0 = tx*4;
        float pai = acc[i][0]*atti[c0] + acc[i][1]*atti[c0+1] + acc[i][2]*atti[c0+2] + acc[i][3]*atti[c0+3];
        float paj = acc[i][0]*attj[c0] + acc[i][1]*attj[c0+1] + acc[i][2]*attj[c0+2] + acc[i][3]*attj[c0+3];
        atomicAdd(&redI[ty*4 + i], pai);
        atomicAdd(&redJ[ty*4 + i], paj);
    }
    __syncthreads();
    if (tid < 64) { d_ai[row0 + tid] = redI[tid]; d_aj[row0 + tid] = redJ[tid]; }
}

// ---------------------------------------------------------------------------
// k_gnn: scores -> leaky_relu -> softmax(20) -> weighted neighbor sum + bias.
// Fused accumulation of the 5 per-d moments needed for bn1 AND bn2 (analytic).
// Block = 256 threads, 64 (b,n) rows per block (4 concurrent x 16 iters).
// ---------------------------------------------------------------------------
__global__ void k_gnn(const float* __restrict__ emb, const float* __restrict__ gnn_bias) {
    __shared__ float scs[4][TK];
    __shared__ float es [4][TK];
    __shared__ int   idxs[4][TK];
    __shared__ float gb[64];
    __shared__ float sred[5*64];
    int tid = threadIdx.x;
    if (tid < 64) gb[tid] = gnn_bias[tid];
    for (int i = tid; i < 5*64; i += 256) sred[i] = 0.f;
    int r4 = tid >> 6, d = tid & 63;
    float sg = 0.f, sgg = 0.f, sge = 0.f, sge2 = 0.f, sgge2 = 0.f;
    __syncthreads();
    for (int it = 0; it < 16; it++) {
        int m = blockIdx.x*64 + it*4 + r4;
        int b = m >> 10, n = m & 1023;
        if (d < TK) {
            int idx = d_topi[n*TK + d];
            float sc = d_ai[m] + d_aemi[n] + d_aj[(b << 10) + idx] + d_aemj[idx];
            sc = sc > 0.f ? sc : NEG*sc;
            scs[r4][d] = sc; idxs[r4][d] = idx;
        }
        __syncthreads();
        if (d < TK) {
            float mx = -FLT_MAX;
            #pragma unroll
            for (int k = 0; k < TK; k++) mx = fmaxf(mx, scs[r4][k]);
            es[r4][d] = __expf(scs[r4][d] - mx);
        }
        __syncthreads();
        float ssum = 0.f;
        #pragma unroll
        for (int k = 0; k < TK; k++) ssum += es[r4][k];
        float inv = 1.f / ssum;
        float acc = 0.f;
        #pragma unroll
        for (int k = 0; k < TK; k++) {
            int idx = idxs[r4][k];
            acc += es[r4][k] * d_xl[((b << 10) + idx)*DD + d];
        }
        float g = acc*inv + gb[d];
        d_gnn[m*DD + d] = g;
        float e  = emb[(n << 6) + d];
        float ge = g*e;
        sg += g; sgg += g*g; sge += ge; sge2 += ge*e; sgge2 += ge*ge;
        __syncthreads();
    }
    atomicAdd(&sred[0*64 + d], sg);
    atomicAdd(&sred[1*64 + d], sgg);
    atomicAdd(&sred[2*64 + d], sge);
    atomicAdd(&sred[3*64 + d], sge2);
    atomicAdd(&sred[4*64 + d], sgge2);
    __syncthreads();
    for (int i = tid; i < 5*64; i += 256) atomicAdd(&d_stats[i], sred[i]);
}

// ---------------------------------------------------------------------------
// k_params: finalize bn1 affine (A1,C1) and bn2 affine (A2,C2) analytically.
//   t = (A1*g + C1) * e ;  E[t], E[t^2] from the 5 g-moments + emb moments.
// ---------------------------------------------------------------------------
__global__ void k_params(const float* __restrict__ emb,
                         const float* __restrict__ g1, const float* __restrict__ b1,
                         const float* __restrict__ g2, const float* __restrict__ b2) {
    __shared__ float sE[4][64], sE2[4][64];
    int tid = threadIdx.x, d = tid & 63, grp = tid >> 6;
    float se = 0.f, see = 0.f;
    for (int n = grp; n < NN; n += 4) {
        float e = emb[n*DD + d];
        se += e; see += e*e;
    }
    sE[grp][d] = se; sE2[grp][d] = see;
    __syncthreads();
    if (tid < 64) {
        float Se  = (sE[0][d] + sE[1][d] + sE[2][d] + sE[3][d]) * (float)BB;
        float See = (sE2[0][d] + sE2[1][d] + sE2[2][d] + sE2[3][d]) * (float)BB;
        const float Minv = 1.f / (float)(BB*NN);
        float Sg    = d_stats[0*64 + d];
        float Sgg   = d_stats[1*64 + d];
        float Sge   = d_stats[2*64 + d];
        float Sge2  = d_stats[3*64 + d];
        float Sgge2 = d_stats[4*64 + d];
        float mu1 = Sg * Minv;
        float var1 = Sgg * Minv - mu1*mu1;
        float A1 = g1[d] * rsqrtf(var1 + EPSBN);
        float C1 = b1[d] - A1*mu1;
        float mu2 = (A1*Sge + C1*Se) * Minv;
        float Et2 = (A1*A1*Sgge2 + 2.f*A1*C1*Sge2 + C1*C1*See) * Minv;
        float var2 = Et2 - mu2*mu2;
        float A2 = g2[d] * rsqrtf(var2 + EPSBN);
        float C2 = b2[d] - A2*mu2;
        d_params[0*64 + d] = A1; d_params[1*64 + d] = C1;
        d_params[2*64 + d] = A2; d_params[3*64 + d] = C2;
    }
}

// ---------------------------------------------------------------------------
// k_out: out = relu(A2*((A1*g+C1)*e)+C2), pred = out . out_w + out_b.
// ---------------------------------------------------------------------------
__global__ void k_out(const float* __restrict__ emb, const float* __restrict__ out_w,
                      const float* __restrict__ out_b,
                      float* __restrict__ pred, float* __restrict__ outbuf) {
    __shared__ float A1[64], C1[64], A2[64], C2[64], ow[64];
    __shared__ float wp[8];
    int tid = threadIdx.x;
    if (tid < 64) {
        A1[tid] = d_params[0*64 + tid]; C1[tid] = d_params[1*64 + tid];
        A2[tid] = d_params[2*64 + tid]; C2[tid] = d_params[3*64 + tid];
        ow[tid] = out_w[tid];
    }
    __syncthreads();
    int r4 = tid >> 6, d = tid & 63, lane = tid & 31, w = tid >> 5;
    float ob = out_b[0];
    for (int it = 0; it < 16; it++) {
        int m = blockIdx.x*64 + it*4 + r4;
        int n = m & 1023;
        float g = d_gnn[m*DD + d];
        float e = emb[(n << 6) + d];
        float t = (A1[d]*g + C1[d]) * e;
        float o = fmaxf(fmaf(A2[d], t, C2[d]), 0.f);
        outbuf[m*DD + d] = o;
        float pr = o * ow[d];
        #pragma unroll
        for (int off = 16; off; off >>= 1) pr += __shfl_down_sync(0xffffffffu, pr, off);
        if (lane == 0) wp[w] = pr;
        __syncthreads();
        if (tid < 4) pred[blockIdx.x*64 + it*4 + tid] = wp[2*tid] + wp[2*tid + 1] + ob;
        __syncthreads();
    }
}

// ---------------------------------------------------------------------------
extern "C" void kernel_launch(void* const* d_in, const int* in_sizes, int n_in,
                              void* d_out, int out_size) {
    const float* data     = (const float*)d_in[0];
    // d_in[1] = org_edge_index (unused by the reference)
    const float* emb      = (const float*)d_in[2];
    const float* lin_w    = (const float*)d_in[3];
    const float* att_i    = (const float*)d_in[4];
    const float* att_j    = (const float*)d_in[5];
    const float* att_em_i = (const float*)d_in[6];
    const float* att_em_j = (const float*)d_in[7];
    const float* gnn_bias = (const float*)d_in[8];
    const float* bn1g     = (const float*)d_in[9];
    const float* bn1b     = (const float*)d_in[10];
    const float* bn2g     = (const float*)d_in[11];
    const float* bn2b     = (const float*)d_in[12];
    const float* out_w    = (const float*)d_in[13];
    const float* out_b    = (const float*)d_in[14];

    float* pred = (float*)d_out;              // (B,N)   = 65536 floats
    float* outb = (float*)d_out + BB*NN;      // (B,N,D) = 4194304 floats

    k_prep  <<<NN, 64>>>(emb, att_em_i, att_em_j);
    k_scores<<<dim3(16,16), 256>>>(emb);
    k_topk  <<<NN, 256>>>();
    k_xl    <<<1024, 256>>>(data, lin_w, att_i, att_j);
    k_gnn   <<<1024, 256>>>(emb, gnn_bias);
    k_params<<<1, 256>>>(emb, bn1g, bn1b, bn2g, bn2b);
    k_out   <<<1024, 256>>>(emb, out_w, out_b, pred, outb);
}

// round 10
// speedup vs baseline: 1.0540x; 1.0030x over previous
#include <cuda_runtime.h>
#include <math.h>
#include <float.h>

// Problem constants
#define NN   1024
#define FF   64
#define DD   64
#define TK   20
#define BB   64
#define EPSBN 1e-5f
#define NEG  0.2f

// Scratch (device globals: allocation-free)
__device__ float d_xl[BB*NN*DD];     // 16 MB
__device__ float d_gnn[BB*NN*DD];    // 16 MB
__device__ float d_S[NN*NN];         // 4 MB  cosine-equivalent scores
__device__ float d_u[NN*DD];         // normalized embedding rows
__device__ float d_ai[BB*NN];
__device__ float d_aj[BB*NN];
__device__ float d_aemi[NN];
__device__ float d_aemj[NN];
__device__ int   d_topi[NN*TK];
__device__ float d_stats[5*DD];      // Sg, Sgg, Sge, Sge2, Sgge2
__device__ float d_params[4*DD];     // A1, C1, A2, C2

// ---------------------------------------------------------------------------
// k_prep: per-node norm, u = w/||w||, aem_i = w.att_em_i, aem_j = w.att_em_j.
// Block 0 also zeroes the stats accumulator (replay-safe: runs every launch).
// ---------------------------------------------------------------------------
__global__ void k_prep(const float* __restrict__ emb,
                       const float* __restrict__ att_em_i,
                       const float* __restrict__ att_em_j) {
    int j = blockIdx.x, d = threadIdx.x;
    if (blockIdx.x == 0) {
        for (int i = threadIdx.x; i < 5*DD; i += 64) d_stats[i] = 0.f;
    }
    float v  = emb[j*DD + d];
    float p0 = v*v;
    float p1 = v*att_em_i[d];
    float p2 = v*att_em_j[d];
    #pragma unroll
    for (int off = 16; off; off >>= 1) {
        p0 += __shfl_down_sync(0xffffffffu, p0, off);
        p1 += __shfl_down_sync(0xffffffffu, p1, off);
        p2 += __shfl_down_sync(0xffffffffu, p2, off);
    }
    __shared__ float w0[2], w1[2], w2[2];
    int lane = d & 31, wrp = d >> 5;
    if (lane == 0) { w0[wrp] = p0; w1[wrp] = p1; w2[wrp] = p2; }
    __syncthreads();
    float nrm2 = w0[0] + w0[1];
    float inv  = rsqrtf(nrm2);
    d_u[j*DD + d] = v * inv;
    if (d == 0) {
        d_aemi[j] = w1[0] + w1[1];
        d_aemj[j] = w2[0] + w2[1];
    }
}

// ---------------------------------------------------------------------------
// k_scores: S = emb @ u^T  (1024x1024x64). 64x64 output tile per block.
// ---------------------------------------------------------------------------
__global__ void k_scores(const float* __restrict__ emb) {
    __shared__ __align__(16) float As[64][68];   // As[d][row]
    __shared__ __align__(16) float Bs[64][68];   // Bs[d][col]
    int i0 = blockIdx.y * 64, j0 = blockIdx.x * 64;
    int tid = threadIdx.x;
    for (int idx = tid; idx < 4096; idx += 256) {
        int r = idx >> 6, dd = idx & 63;
        As[dd][r] = emb[(i0 + r)*DD + dd];
        Bs[dd][r] = d_u[(j0 + r)*DD + dd];
    }
    __syncthreads();
    int tx = tid & 15, ty = tid >> 4;
    float acc[4][4] = {};
    #pragma unroll
    for (int dd = 0; dd < 64; dd++) {
        float4 a = *(const float4*)&As[dd][ty*4];
        float4 b = *(const float4*)&Bs[dd][tx*4];
        acc[0][0] += a.x*b.x; acc[0][1] += a.x*b.y; acc[0][2] += a.x*b.z; acc[0][3] += a.x*b.w;
        acc[1][0] += a.y*b.x; acc[1][1] += a.y*b.y; acc[1][2] += a.y*b.z; acc[1][3] += a.y*b.w;
        acc[2][0] += a.z*b.x; acc[2][1] += a.z*b.y; acc[2][2] += a.z*b.z; acc[2][3] += a.z*b.w;
        acc[3][0] += a.w*b.x; acc[3][1] += a.w*b.y; acc[3][2] += a.w*b.z; acc[3][3] += a.w*b.w;
    }
    #pragma unroll
    for (int i = 0; i < 4; i++) {
        float4 v = make_float4(acc[i][0], acc[i][1], acc[i][2], acc[i][3]);
        *(float4*)&d_S[(i0 + ty*4 + i)*NN + j0 + tx*4] = v;
    }
}

// ---------------------------------------------------------------------------
// k_topk: per-row top-20 by iterative argmax (tie -> lowest index, jax-compat).
// ---------------------------------------------------------------------------
__global__ void k_topk() {
    __shared__ float s[NN];
    __shared__ float bv[256];
    __shared__ int   bi[256];
    int row = blockIdx.x, tid = threadIdx.x;
    for (int j = tid; j < NN; j += 256) s[j] = d_S[row*NN + j];
    __syncthreads();
    for (int t = 0; t < TK; t++) {
        float best = -FLT_MAX; int bidx = NN;
        for (int j = tid; j < NN; j += 256) {
            float v = s[j];
            if (v > best) { best = v; bidx = j; }   // strict > keeps smallest j on ties
        }
        bv[tid] = best; bi[tid] = bidx;
        __syncthreads();
        #pragma unroll
        for (int off = 128; off; off >>= 1) {
            if (tid < off) {
                float v = bv[tid + off]; int i2 = bi[tid + off];
                if (v > bv[tid] || (v == bv[tid] && i2 < bi[tid])) { bv[tid] = v; bi[tid] = i2; }
            }
            __syncthreads();
        }
        if (tid == 0) { d_topi[row*TK + t] = bi[0]; s[bi[0]] = -FLT_MAX; }
        __syncthreads();
    }
}

// ---------------------------------------------------------------------------
// k_xl: xl = data @ lin_w (65536x64 @ 64x64), fused per-row dots with
// att_i / att_j. 64 rows per block, 4x4 register tile per thread.
// ---------------------------------------------------------------------------
__global__ void k_xl(const float* __restrict__ data, const float* __restrict__ lw,
                     const float* __restrict__ att_i, const float* __restrict__ att_j) {
    __shared__ __align__(16) float Ws[64][64];   // Ws[f][c]
    __shared__ __align__(16) float Dt[64][68];   // Dt[f][r]
    __shared__ float atti[64], attj[64], redI[64], redJ[64];
    int tid = threadIdx.x;
    int row0 = blockIdx.x * 64;
    for (int idx = tid; idx < 4096; idx += 256) {
        ((float*)Ws)[idx] = lw[idx];
        int r = idx >> 6, f = idx & 63;
        Dt[f][r] = data[(row0 + r)*FF + f];
    }
    if (tid < 64) { atti[tid] = att_i[tid]; attj[tid] = att_j[tid]; redI[tid] = 0.f; redJ[tid] = 0.f; }
    __syncthreads();
    int tx = tid & 15, ty = tid >> 4;
    float acc[4][4] = {};
    #pragma unroll
    for (int f = 0; f < 64; f++) {
        float4 a = *(const float4*)&Dt[f][ty*4];
        float4 b = *(const float4*)&Ws[f][tx*4];
        acc[0][0] += a.x*b.x; acc[0][1] += a.x*b.y; acc[0][2] += a.x*b.z; acc[0][3] += a.x*b.w;
        acc[1][0] += a.y*b.x; acc[1][1] += a.y*b.y; acc[1][2] += a.y*b.z; acc[1][3] += a.y*b.w;
        acc[2][0] += a.z*b.x; acc[2][1] += a.z*b.y; acc[2][2] += a.z*b.z; acc[2][3] += a.z*b.w;
        acc[3][0] += a.w*b.x; acc[3][1] += a.w*b.y; acc[3][2] += a.w*b.z; acc[3][3] += a.w*b.w;
    }
    #pragma unroll
    for (int i = 0; i < 4; i++) {
        int gr = row0 + ty*4 + i;
        float4 v = make_float4(acc[i][0], acc[i][1], acc[i][2], acc[i][3]);
        *(float4*)&d_xl[gr*DD + tx*4] = v;
        int c0 = tx*4;
        float pai = acc[i][0]*atti[c0] + acc[i][1]*atti[c0+1] + acc[i][2]*atti[c0+2] + acc[i][3]*atti[c0+3];
        float paj = acc[i][0]*attj[c0] + acc[i][1]*attj[c0+1] + acc[i][2]*attj[c0+2] + acc[i][3]*attj[c0+3];
        atomicAdd(&redI[ty*4 + i], pai);
        atomicAdd(&redJ[ty*4 + i], paj);
    }
    __syncthreads();
    if (tid < 64) { d_ai[row0 + tid] = redI[tid]; d_aj[row0 + tid] = redJ[tid]; }
}

// ---------------------------------------------------------------------------
// k_gnn: scores -> leaky_relu -> softmax(20) -> weighted neighbor sum + bias.
// Fused accumulation of the 5 per-d moments needed for bn1 AND bn2 (analytic).
// Block = 256 threads, 64 (b,n) rows per block (4 concurrent x 16 iters).
// ---------------------------------------------------------------------------
__global__ void k_gnn(const float* __restrict__ emb, const float* __restrict__ gnn_bias) {
    __shared__ float scs[4][TK];
    __shared__ float es [4][TK];
    __shared__ int   idxs[4][TK];
    __shared__ float gb[64];
    __shared__ float sred[5*64];
    int tid = threadIdx.x;
    if (tid < 64) gb[tid] = gnn_bias[tid];
    for (int i = tid; i < 5*64; i += 256) sred[i] = 0.f;
    int r4 = tid >> 6, d = tid & 63;
    float sg = 0.f, sgg = 0.f, sge = 0.f, sge2 = 0.f, sgge2 = 0.f;
    __syncthreads();
    for (int it = 0; it < 16; it++) {
        int m = blockIdx.x*64 + it*4 + r4;
        int b = m >> 10, n = m & 1023;
        if (d < TK) {
            int idx = d_topi[n*TK + d];
            float sc = d_ai[m] + d_aemi[n] + d_aj[(b << 10) + idx] + d_aemj[idx];
            sc = sc > 0.f ? sc : NEG*sc;
            scs[r4][d] = sc; idxs[r4][d] = idx;
        }
        __syncthreads();
        if (d < TK) {
            float mx = -FLT_MAX;
            #pragma unroll
            for (int k = 0; k < TK; k++) mx = fmaxf(mx, scs[r4][k]);
            es[r4][d] = __expf(scs[r4][d] - mx);
        }
        __syncthreads();
        float ssum = 0.f;
        #pragma unroll
        for (int k = 0; k < TK; k++) ssum += es[r4][k];
        float inv = 1.f / ssum;
        float acc = 0.f;
        #pragma unroll
        for (int k = 0; k < TK; k++) {
            int idx = idxs[r4][k];
            acc += es[r4][k] * d_xl[((b << 10) + idx)*DD + d];
        }
        float g = acc*inv + gb[d];
        d_gnn[m*DD + d] = g;
        float e  = emb[(n << 6) + d];
        float ge = g*e;
        sg += g; sgg += g*g; sge += ge; sge2 += ge*e; sgge2 += ge*ge;
        __syncthreads();
    }
    atomicAdd(&sred[0*64 + d], sg);
    atomicAdd(&sred[1*64 + d], sgg);
    atomicAdd(&sred[2*64 + d], sge);
    atomicAdd(&sred[3*64 + d], sge2);
    atomicAdd(&sred[4*64 + d], sgge2);
    __syncthreads();
    for (int i = tid; i < 5*64; i += 256) atomicAdd(&d_stats[i], sred[i]);
}

// ---------------------------------------------------------------------------
// k_params: finalize bn1 affine (A1,C1) and bn2 affine (A2,C2) analytically.
//   t = (A1*g + C1) * e ;  E[t], E[t^2] from the 5 g-moments + emb moments.
// ---------------------------------------------------------------------------
__global__ void k_params(const float* __restrict__ emb,
                         const float* __restrict__ g1, const float* __restrict__ b1,
                         const float* __restrict__ g2, const float* __restrict__ b2) {
    __shared__ float sE[4][64], sE2[4][64];
    int tid = threadIdx.x, d = tid & 63, grp = tid >> 6;
    float se = 0.f, see = 0.f;
    for (int n = grp; n < NN; n += 4) {
        float e = emb[n*DD + d];
        se += e; see += e*e;
    }
    sE[grp][d] = se; sE2[grp][d] = see;
    __syncthreads();
    if (tid < 64) {
        float Se  = (sE[0][d] + sE[1][d] + sE[2][d] + sE[3][d]) * (float)BB;
        float See = (sE2[0][d] + sE2[1][d] + sE2[2][d] + sE2[3][d]) * (float)BB;
        const float Minv = 1.f / (float)(BB*NN);
        float Sg    = d_stats[0*64 + d];
        float Sgg   = d_stats[1*64 + d];
        float Sge   = d_stats[2*64 + d];
        float Sge2  = d_stats[3*64 + d];
        float Sgge2 = d_stats[4*64 + d];
        float mu1 = Sg * Minv;
        float var1 = Sgg * Minv - mu1*mu1;
        float A1 = g1[d] * rsqrtf(var1 + EPSBN);
        float C1 = b1[d] - A1*mu1;
        float mu2 = (A1*Sge + C1*Se) * Minv;
        float Et2 = (A1*A1*Sgge2 + 2.f*A1*C1*Sge2 + C1*C1*See) * Minv;
        float var2 = Et2 - mu2*mu2;
        float A2 = g2[d] * rsqrtf(var2 + EPSBN);
        float C2 = b2[d] - A2*mu2;
        d_params[0*64 + d] = A1; d_params[1*64 + d] = C1;
        d_params[2*64 + d] = A2; d_params[3*64 + d] = C2;
    }
}

// ---------------------------------------------------------------------------
// k_out: out = relu(A2*((A1*g+C1)*e)+C2), pred = out . out_w + out_b.
// ---------------------------------------------------------------------------
__global__ void k_out(const float* __restrict__ emb, const float* __restrict__ out_w,
                      const float* __restrict__ out_b,
                      float* __restrict__ pred, float* __restrict__ outbuf) {
    __shared__ float A1[64], C1[64], A2[64], C2[64], ow[64];
    __shared__ float wp[8];
    int tid = threadIdx.x;
    if (tid < 64) {
        A1[tid] = d_params[0*64 + tid]; C1[tid] = d_params[1*64 + tid];
        A2[tid] = d_params[2*64 + tid]; C2[tid] = d_params[3*64 + tid];
        ow[tid] = out_w[tid];
    }
    __syncthreads();
    int r4 = tid >> 6, d = tid & 63, lane = tid & 31, w = tid >> 5;
    float ob = out_b[0];
    for (int it = 0; it < 16; it++) {
        int m = blockIdx.x*64 + it*4 + r4;
        int n = m & 1023;
        float g = d_gnn[m*DD + d];
        float e = emb[(n << 6) + d];
        float t = (A1[d]*g + C1[d]) * e;
        float o = fmaxf(fmaf(A2[d], t, C2[d]), 0.f);
        outbuf[m*DD + d] = o;
        float pr = o * ow[d];
        #pragma unroll
        for (int off = 16; off; off >>= 1) pr += __shfl_down_sync(0xffffffffu, pr, off);
        if (lane == 0) wp[w] = pr;
        __syncthreads();
        if (tid < 4) pred[blockIdx.x*64 + it*4 + tid] = wp[2*tid] + wp[2*tid + 1] + ob;
        __syncthreads();
    }
}

// ---------------------------------------------------------------------------
extern "C" void kernel_launch(void* const* d_in, const int* in_sizes, int n_in,
                              void* d_out, int out_size) {
    const float* data     = (const float*)d_in[0];
    // d_in[1] = org_edge_index (unused by the reference)
    const float* emb      = (const float*)d_in[2];
    const float* lin_w    = (const float*)d_in[3];
    const float* att_i    = (const float*)d_in[4];
    const float* att_j    = (const float*)d_in[5];
    const float* att_em_i = (const float*)d_in[6];
    const float* att_em_j = (const float*)d_in[7];
    const float* gnn_bias = (const float*)d_in[8];
    const float* bn1g     = (const float*)d_in[9];
    const float* bn1b     = (const float*)d_in[10];
    const float* bn2g     = (const float*)d_in[11];
    const float* bn2b     = (const float*)d_in[12];
    const float* out_w    = (const float*)d_in[13];
    const float* out_b    = (const float*)d_in[14];

    float* pred = (float*)d_out;              // (B,N)   = 65536 floats
    float* outb = (float*)d_out + BB*NN;      // (B,N,D) = 4194304 floats

    k_prep  <<<NN, 64>>>(emb, att_em_i, att_em_j);
    k_scores<<<dim3(16,16), 256>>>(emb);
    k_topk  <<<NN, 256>>>();
    k_xl    <<<1024, 256>>>(data, lin_w, att_i, att_j);
    k_gnn   <<<1024, 256>>>(emb, gnn_bias);
    k_params<<<1, 256>>>(emb, bn1g, bn1b, bn2g, bn2b);
    k_out   <<<1024, 256>>>(emb, out_w, out_b, pred, outb);
}